// round 14
// baseline (speedup 1.0000x reference)
#include <cuda_runtime.h>
#include <cstdint>

// ---------------- problem constants ----------------
#define HV 128
#define HT 17
#define KTYPES 8
#define DIM 290            // 2*(HV+HT)
#define DPAD 320           // padded K, 10 chunks of 32
#define OGATES 640         // 5*HV
#define NN 200000
#define BM 128
#define MAXTILES 1571
#define MAXROWS (MAXTILES*BM)

#define CS 36              // smem row stride (f32), conflict-free frag loads
#define ACH (128*CS)       // floats per chunk buffer (4608)
// smem float offsets
#define OFF_A   0
#define OFF_B   (10*ACH)           // 46080
#define OFF_TBL (12*ACH)           // 55296 (ints: node[128], li[128], ri[128])
#define SM_FLOATS (OFF_TBL + 384)
#define SMBYTES (SM_FLOATS*4)      // 222720 B

// ---------------- device scratch ----------------
__device__ int   g_cnt[KTYPES];
__device__ int   g_fill[KTYPES];
__device__ int   g_tile_type[MAXTILES];
__device__ int   g_perm[MAXROWS];                 // row -> node (-1 = pad)
__device__ float g_Wp[KTYPES*OGATES*DPAD];        // padded, tf32-rounded weights

// ---------------- helpers ----------------
__device__ __forceinline__ uint32_t smem_u32(const void* p) {
    uint32_t a;
    asm("{ .reg .u64 t; cvta.to.shared.u64 t, %1; cvt.u32.u64 %0, t; }" : "=r"(a) : "l"(p));
    return a;
}
__device__ __forceinline__ float to_tf32(float x) {
    float r;
    asm("cvt.rna.tf32.f32 %0, %1;" : "=f"(r) : "f"(x));
    return r;
}
__device__ __forceinline__ float sigm(float x) { return 1.f / (1.f + expf(-x)); }

#define CP_ASYNC16(dst, src) \
    asm volatile("cp.async.cg.shared.global [%0], [%1], 16;" :: "r"(dst), "l"(src))
#define CP_COMMIT() asm volatile("cp.async.commit_group;" ::: "memory")
#define CP_WAIT0()  asm volatile("cp.async.wait_group 0;" ::: "memory")

__device__ __forceinline__ void mma_tf32(float* c, const uint32_t* a, const uint32_t* b) {
    asm volatile(
        "mma.sync.aligned.m16n8k8.row.col.f32.tf32.tf32.f32 "
        "{%0,%1,%2,%3}, {%4,%5,%6,%7}, {%8,%9}, {%0,%1,%2,%3};"
        : "+f"(c[0]), "+f"(c[1]), "+f"(c[2]), "+f"(c[3])
        : "r"(a[0]), "r"(a[1]), "r"(a[2]), "r"(a[3]), "r"(b[0]), "r"(b[1]));
}

// ---------------- setup kernels ----------------
__global__ void k_init() {
    int i = blockIdx.x * blockDim.x + threadIdx.x;
    if (i < MAXROWS) g_perm[i] = -1;
    if (i < MAXTILES) g_tile_type[i] = 0;
    if (i < KTYPES) g_cnt[i] = 0;
}

__global__ void k_hist(const int* __restrict__ parent_type) {
    __shared__ int loc[KTYPES];
    int t = threadIdx.x;
    if (t < KTYPES) loc[t] = 0;
    __syncthreads();
    int i = blockIdx.x * blockDim.x + t;
    if (i < NN) atomicAdd(&loc[parent_type[i]], 1);
    __syncthreads();
    if (t < KTYPES && loc[t]) atomicAdd(&g_cnt[t], loc[t]);
}

__global__ void k_offsets() {
    int off = 0;
    for (int k = 0; k < KTYPES; k++) {
        g_fill[k] = off;
        int tiles = (g_cnt[k] + BM - 1) / BM;
        for (int t = 0; t < tiles; t++) g_tile_type[off / BM + t] = k;
        off += tiles * BM;
    }
}

__global__ void k_scatter(const int* __restrict__ parent_type) {
    __shared__ int loc[KTYPES];
    __shared__ int base[KTYPES];
    int t = threadIdx.x;
    if (t < KTYPES) loc[t] = 0;
    __syncthreads();
    int i = blockIdx.x * blockDim.x + t;
    int k = 0, my = 0;
    if (i < NN) {
        k = parent_type[i];
        my = atomicAdd(&loc[k], 1);
    }
    __syncthreads();
    if (t < KTYPES && loc[t]) base[t] = atomicAdd(&g_fill[t], loc[t]);
    __syncthreads();
    if (i < NN) g_perm[base[k] + my] = i;
}

__global__ void k_padW(const float* __restrict__ W) {
    int idx = blockIdx.x * blockDim.x + threadIdx.x;
    if (idx >= KTYPES * OGATES * DPAD) return;
    int og = idx / DPAD;
    int d  = idx % DPAD;
    g_Wp[idx] = (d < DIM) ? to_tf32(W[(size_t)og * DIM + d]) : 0.f;
}

// ---------------- fused GEMM + LSTM kernel ----------------
__device__ __forceinline__ void load_B(const float* __restrict__ src,
                                       uint32_t sdst, int kc, int tid) {
#pragma unroll
    for (int i = 0; i < 4; i++) {
        int f = tid + i * 256;
        int r = f >> 3, c = f & 7;
        CP_ASYNC16(sdst + (uint32_t)(r * CS + c * 4) * 4u,
                   src + (size_t)r * DPAD + kc * 32 + c * 4);
    }
}

__global__ void __launch_bounds__(256, 1)
k_fused(const float* __restrict__ h_pool, const float* __restrict__ c_pool,
        const float* __restrict__ t_pool, const int* __restrict__ child_idx,
        const float* __restrict__ b, float* __restrict__ out) {
    extern __shared__ float sm[];
    int* sNode = (int*)(sm + OFF_TBL);
    int* sLi   = sNode + 128;
    int* sRi   = sNode + 256;
    uint32_t sB_bytes = smem_u32(sm + OFF_B);

    int tid = threadIdx.x;
    int lane = tid & 31, wid = tid >> 5;
    int wm = wid & 3;          // warp row block: rows wm*32 .. +31
    int wn = wid >> 2;         // warp col block: cols wn*64 .. +63
    int g = lane >> 2, t = lane & 3;

    int tile = blockIdx.x;
    int typ  = g_tile_type[tile];
    int row0 = tile * BM;

    // ---- row tables ----
    if (tid < 128) {
        int nd = g_perm[row0 + tid];
        sNode[tid] = nd;
        int li = 0, ri = 0;
        if (nd >= 0) { li = child_idx[2 * nd]; ri = child_idx[2 * nd + 1]; }
        sLi[tid] = li;
        sRi[tid] = ri;
    }
    __syncthreads();

    // ---- gather A tile directly into smem (tf32-rounded) ----
    {
        int r = tid >> 1;
        int half = tid & 1;
        int nd = sNode[r];
        int li = sLi[r], ri = sRi[r];
        const float* hl = h_pool + (size_t)li * HV;
        const float* hr = h_pool + (size_t)ri * HV;
        const float* tl = t_pool + (size_t)li * HT;
        const float* tr = t_pool + (size_t)ri * HT;
        int j0 = half * 160;
        for (int j = j0; j < j0 + 160; j++) {
            float v = 0.f;
            if (nd >= 0) {
                if (j < HV)               v = hl[j];
                else if (j < HV + HT)     v = tl[j - HV];
                else if (j < 2*HV + HT)   v = hr[j - (HV + HT)];
                else if (j < DIM)         v = tr[j - (2*HV + HT)];
            }
            sm[OFF_A + (j >> 5) * ACH + r * CS + (j & 31)] = to_tf32(v);
        }
    }

    const float* Wtyp = g_Wp + (size_t)typ * OGATES * DPAD;
    const float* bk   = b + (size_t)typ * OGATES;
    const int gseq[6] = {0, 3, 1, 2, 4, 4};   // i, u, fl, fr, o

    __syncthreads();

    // preload (gate 0, chunk 0) into buf 0
    load_B(Wtyp + (size_t)gseq[0] * 128 * DPAD, sB_bytes, 0, tid);
    CP_COMMIT();
    CP_WAIT0();
    __syncthreads();

    float carry[2][8][4];

#pragma unroll
    for (int gp = 0; gp < 5; gp++) {
        const int gidx = gseq[gp];
        float acc[2][8][4];
#pragma unroll
        for (int mt = 0; mt < 2; mt++)
#pragma unroll
            for (int nt = 0; nt < 8; nt++)
#pragma unroll
                for (int e = 0; e < 4; e++) acc[mt][nt][e] = 0.f;

        for (int kc = 0; kc < 10; kc++) {
            int cid = gp * 10 + kc;
            int buf = cid & 1;
            if (cid < 49) {
                int nk = (kc == 9) ? 0 : kc + 1;
                const float* Bn = Wtyp + (size_t)gseq[(kc == 9) ? gp + 1 : gp] * 128 * DPAD;
                load_B(Bn, sB_bytes + (uint32_t)((buf ^ 1) * ACH) * 4u, nk, tid);
                CP_COMMIT();
            }
            const float* Ac = sm + OFF_A + kc * ACH;
            const float* Bc = sm + OFF_B + buf * ACH;
#pragma unroll
            for (int ks = 0; ks < 4; ks++) {
                int kk = ks * 8;
                uint32_t afr[2][4], bfr[8][2];
#pragma unroll
                for (int mt = 0; mt < 2; mt++) {
                    int rb = wm * 32 + mt * 16;
                    afr[mt][0] = __float_as_uint(Ac[(rb + g) * CS + kk + t]);
                    afr[mt][1] = __float_as_uint(Ac[(rb + g + 8) * CS + kk + t]);
                    afr[mt][2] = __float_as_uint(Ac[(rb + g) * CS + kk + t + 4]);
                    afr[mt][3] = __float_as_uint(Ac[(rb + g + 8) * CS + kk + t + 4]);
                }
#pragma unroll
                for (int nt = 0; nt < 8; nt++) {
                    int cb = wn * 64 + nt * 8;
                    bfr[nt][0] = __float_as_uint(Bc[(cb + g) * CS + kk + t]);
                    bfr[nt][1] = __float_as_uint(Bc[(cb + g) * CS + kk + t + 4]);
                }
#pragma unroll
                for (int mt = 0; mt < 2; mt++)
#pragma unroll
                    for (int nt = 0; nt < 8; nt++)
                        mma_tf32(acc[mt][nt], afr[mt], bfr[nt]);
            }

            // ---- gate finalize (overlaps next chunk's cp.async flight) ----
            if (kc == 9) {
#pragma unroll
                for (int mt = 0; mt < 2; mt++) {
#pragma unroll
                    for (int h8 = 0; h8 < 2; h8++) {
                        int r = wm * 32 + mt * 16 + g + h8 * 8;
                        int nd = sNode[r];
                        int li = sLi[r], ri = sRi[r];
#pragma unroll
                        for (int nt = 0; nt < 8; nt++) {
                            int jj = wn * 64 + nt * 8 + t * 2;
                            float a0 = acc[mt][nt][h8*2+0] + bk[gidx * 128 + jj];
                            float a1 = acc[mt][nt][h8*2+1] + bk[gidx * 128 + jj + 1];
                            float* cy = &carry[mt][nt][h8*2];
                            if (gp == 0) {            // i
                                cy[0] = sigm(a0);
                                cy[1] = sigm(a1);
                            } else if (gp == 1) {     // u
                                cy[0] *= tanhf(a0);
                                cy[1] *= tanhf(a1);
                            } else if (gp == 2) {     // fl
                                cy[0] += sigm(a0) * __ldg(c_pool + (size_t)li * HV + jj);
                                cy[1] += sigm(a1) * __ldg(c_pool + (size_t)li * HV + jj + 1);
                            } else if (gp == 3) {     // fr -> c, store c
                                cy[0] += sigm(a0) * __ldg(c_pool + (size_t)ri * HV + jj);
                                cy[1] += sigm(a1) * __ldg(c_pool + (size_t)ri * HV + jj + 1);
                                if (nd >= 0)
                                    *(float2*)(out + (size_t)nd * 256 + 128 + jj) =
                                        make_float2(cy[0], cy[1]);
                            } else {                  // o -> h, store h
                                if (nd >= 0)
                                    *(float2*)(out + (size_t)nd * 256 + jj) =
                                        make_float2(sigm(a0) * tanhf(cy[0]),
                                                    sigm(a1) * tanhf(cy[1]));
                            }
                        }
                    }
                }
            }

            if (cid < 49) CP_WAIT0();
            __syncthreads();
        }
    }
}

// ---------------- launch ----------------
extern "C" void kernel_launch(void* const* d_in, const int* in_sizes, int n_in,
                              void* d_out, int out_size) {
    const float* h_pool      = (const float*)d_in[0];
    const float* c_pool      = (const float*)d_in[1];
    const float* t_pool      = (const float*)d_in[2];
    const int*   child_idx   = (const int*)d_in[3];
    const int*   parent_type = (const int*)d_in[4];
    const float* W           = (const float*)d_in[5];
    const float* b           = (const float*)d_in[6];
    float* out = (float*)d_out;

    cudaFuncSetAttribute(k_fused, cudaFuncAttributeMaxDynamicSharedMemorySize, SMBYTES);

    k_init<<<(MAXROWS + 255) / 256, 256>>>();
    k_hist<<<(NN + 255) / 256, 256>>>(parent_type);
    k_offsets<<<1, 1>>>();
    k_scatter<<<(NN + 255) / 256, 256>>>(parent_type);
    k_padW<<<(KTYPES * OGATES * DPAD + 255) / 256, 256>>>(W);
    k_fused<<<MAXTILES, 256, SMBYTES>>>(h_pool, c_pool, t_pool, child_idx, b, out);
}

// round 15
// speedup vs baseline: 1.2065x; 1.2065x over previous
#include <cuda_runtime.h>
#include <cstdint>

// ---------------- problem constants ----------------
#define HV 128
#define HT 17
#define KTYPES 8
#define DIM 290            // 2*(HV+HT)
#define DPAD 320           // padded K, 10 chunks of 32
#define OGATES 640         // 5*HV
#define NN 200000
#define BM 128
#define MAXTILES 1571
#define MAXROWS (MAXTILES*BM)
#define THREADS 512

#define CS 36              // smem row stride (f32), conflict-free frag loads
#define ACH (128*CS)       // floats per chunk buffer (4608)
// smem float offsets
#define OFF_A   0
#define OFF_B   (10*ACH)           // 46080
#define OFF_TBL (12*ACH)           // 55296 (ints: node[128], li[128], ri[128])
#define SM_FLOATS (OFF_TBL + 384)
#define SMBYTES (SM_FLOATS*4)      // 222720 B

// ---------------- device scratch ----------------
__device__ int   g_cnt[KTYPES];
__device__ int   g_fill[KTYPES];
__device__ int   g_tile_type[MAXTILES];
__device__ int   g_perm[MAXROWS];                 // row -> node (-1 = pad)
__device__ float g_Wp[KTYPES*OGATES*DPAD];        // padded, tf32-rounded weights

// ---------------- helpers ----------------
__device__ __forceinline__ uint32_t smem_u32(const void* p) {
    uint32_t a;
    asm("{ .reg .u64 t; cvta.to.shared.u64 t, %1; cvt.u32.u64 %0, t; }" : "=r"(a) : "l"(p));
    return a;
}
__device__ __forceinline__ float to_tf32(float x) {
    float r;
    asm("cvt.rna.tf32.f32 %0, %1;" : "=f"(r) : "f"(x));
    return r;
}
__device__ __forceinline__ float sigm(float x) { return 1.f / (1.f + __expf(-x)); }

#define CP_ASYNC16(dst, src) \
    asm volatile("cp.async.cg.shared.global [%0], [%1], 16;" :: "r"(dst), "l"(src))
#define CP_COMMIT() asm volatile("cp.async.commit_group;" ::: "memory")
#define CP_WAIT0()  asm volatile("cp.async.wait_group 0;" ::: "memory")

__device__ __forceinline__ void mma_tf32(float* c, const uint32_t* a, const uint32_t* b) {
    asm volatile(
        "mma.sync.aligned.m16n8k8.row.col.f32.tf32.tf32.f32 "
        "{%0,%1,%2,%3}, {%4,%5,%6,%7}, {%8,%9}, {%0,%1,%2,%3};"
        : "+f"(c[0]), "+f"(c[1]), "+f"(c[2]), "+f"(c[3])
        : "r"(a[0]), "r"(a[1]), "r"(a[2]), "r"(a[3]), "r"(b[0]), "r"(b[1]));
}

// ---------------- setup kernels ----------------
__global__ void k_init() {
    int i = blockIdx.x * blockDim.x + threadIdx.x;
    if (i < MAXROWS) g_perm[i] = -1;
    if (i < MAXTILES) g_tile_type[i] = 0;
    if (i < KTYPES) g_cnt[i] = 0;
}

__global__ void k_hist(const int* __restrict__ parent_type) {
    __shared__ int loc[KTYPES];
    int t = threadIdx.x;
    if (t < KTYPES) loc[t] = 0;
    __syncthreads();
    int i = blockIdx.x * blockDim.x + t;
    if (i < NN) atomicAdd(&loc[parent_type[i]], 1);
    __syncthreads();
    if (t < KTYPES && loc[t]) atomicAdd(&g_cnt[t], loc[t]);
}

__global__ void k_offsets() {
    int off = 0;
    for (int k = 0; k < KTYPES; k++) {
        g_fill[k] = off;
        int tiles = (g_cnt[k] + BM - 1) / BM;
        for (int t = 0; t < tiles; t++) g_tile_type[off / BM + t] = k;
        off += tiles * BM;
    }
}

__global__ void k_scatter(const int* __restrict__ parent_type) {
    __shared__ int loc[KTYPES];
    __shared__ int base[KTYPES];
    int t = threadIdx.x;
    if (t < KTYPES) loc[t] = 0;
    __syncthreads();
    int i = blockIdx.x * blockDim.x + t;
    int k = 0, my = 0;
    if (i < NN) {
        k = parent_type[i];
        my = atomicAdd(&loc[k], 1);
    }
    __syncthreads();
    if (t < KTYPES && loc[t]) base[t] = atomicAdd(&g_fill[t], loc[t]);
    __syncthreads();
    if (i < NN) g_perm[base[k] + my] = i;
}

__global__ void k_padW(const float* __restrict__ W) {
    int idx = blockIdx.x * blockDim.x + threadIdx.x;
    if (idx >= KTYPES * OGATES * DPAD) return;
    int og = idx / DPAD;
    int d  = idx % DPAD;
    g_Wp[idx] = (d < DIM) ? to_tf32(W[(size_t)og * DIM + d]) : 0.f;
}

// ---------------- fused GEMM + LSTM kernel (16 warps) ----------------
__device__ __forceinline__ void load_B(const float* __restrict__ src,
                                       uint32_t sdst, int kc, int tid) {
#pragma unroll
    for (int i = 0; i < 2; i++) {
        int f = tid + i * THREADS;
        int r = f >> 3, c = f & 7;
        CP_ASYNC16(sdst + (uint32_t)(r * CS + c * 4) * 4u,
                   src + (size_t)r * DPAD + kc * 32 + c * 4);
    }
}

__global__ void __launch_bounds__(THREADS, 1)
k_fused(const float* __restrict__ h_pool, const float* __restrict__ c_pool,
        const float* __restrict__ t_pool, const int* __restrict__ child_idx,
        const float* __restrict__ b, float* __restrict__ out) {
    extern __shared__ float sm[];
    int* sNode = (int*)(sm + OFF_TBL);
    int* sLi   = sNode + 128;
    int* sRi   = sNode + 256;
    uint32_t sB_bytes = smem_u32(sm + OFF_B);

    int tid = threadIdx.x;
    int lane = tid & 31, wid = tid >> 5;
    int wm = wid & 3;          // warp row block: rows wm*32 .. +31
    int wn = wid >> 2;         // warp col block: cols wn*32 .. +31  (16 warps: 4x4)
    int g = lane >> 2, t = lane & 3;

    int tile = blockIdx.x;
    int typ  = g_tile_type[tile];
    int row0 = tile * BM;

    // ---- row tables ----
    if (tid < 128) {
        int nd = g_perm[row0 + tid];
        sNode[tid] = nd;
        int li = 0, ri = 0;
        if (nd >= 0) { li = child_idx[2 * nd]; ri = child_idx[2 * nd + 1]; }
        sLi[tid] = li;
        sRi[tid] = ri;
    }
    __syncthreads();

    // ---- gather A tile directly into smem (tf32-rounded); 4 threads/row ----
    {
        int r = tid >> 2;
        int quarter = tid & 3;
        int nd = sNode[r];
        int li = sLi[r], ri = sRi[r];
        const float* hl = h_pool + (size_t)li * HV;
        const float* hr = h_pool + (size_t)ri * HV;
        const float* tl = t_pool + (size_t)li * HT;
        const float* tr = t_pool + (size_t)ri * HT;
        int j0 = quarter * 80;
        for (int j = j0; j < j0 + 80; j++) {
            float v = 0.f;
            if (nd >= 0) {
                if (j < HV)               v = hl[j];
                else if (j < HV + HT)     v = tl[j - HV];
                else if (j < 2*HV + HT)   v = hr[j - (HV + HT)];
                else if (j < DIM)         v = tr[j - (2*HV + HT)];
            }
            sm[OFF_A + (j >> 5) * ACH + r * CS + (j & 31)] = to_tf32(v);
        }
    }

    const float* Wtyp = g_Wp + (size_t)typ * OGATES * DPAD;
    const float* bk   = b + (size_t)typ * OGATES;
    const int gseq[6] = {0, 3, 1, 2, 4, 4};   // i, u, fl, fr, o

    __syncthreads();

    // preload (gate 0, chunk 0) into buf 0
    load_B(Wtyp + (size_t)gseq[0] * 128 * DPAD, sB_bytes, 0, tid);
    CP_COMMIT();
    CP_WAIT0();
    __syncthreads();

    float carry[2][4][4];

#pragma unroll
    for (int gp = 0; gp < 5; gp++) {
        const int gidx = gseq[gp];
        float acc[2][4][4];
#pragma unroll
        for (int mt = 0; mt < 2; mt++)
#pragma unroll
            for (int nt = 0; nt < 4; nt++)
#pragma unroll
                for (int e = 0; e < 4; e++) acc[mt][nt][e] = 0.f;

        for (int kc = 0; kc < 10; kc++) {
            int cid = gp * 10 + kc;
            int buf = cid & 1;
            if (cid < 49) {
                int nk = (kc == 9) ? 0 : kc + 1;
                const float* Bn = Wtyp + (size_t)gseq[(kc == 9) ? gp + 1 : gp] * 128 * DPAD;
                load_B(Bn, sB_bytes + (uint32_t)((buf ^ 1) * ACH) * 4u, nk, tid);
                CP_COMMIT();
            }
            const float* Ac = sm + OFF_A + kc * ACH;
            const float* Bc = sm + OFF_B + buf * ACH;
#pragma unroll
            for (int ks = 0; ks < 4; ks++) {
                int kk = ks * 8;
                uint32_t afr[2][4], bfr[4][2];
#pragma unroll
                for (int mt = 0; mt < 2; mt++) {
                    int rb = wm * 32 + mt * 16;
                    afr[mt][0] = __float_as_uint(Ac[(rb + g) * CS + kk + t]);
                    afr[mt][1] = __float_as_uint(Ac[(rb + g + 8) * CS + kk + t]);
                    afr[mt][2] = __float_as_uint(Ac[(rb + g) * CS + kk + t + 4]);
                    afr[mt][3] = __float_as_uint(Ac[(rb + g + 8) * CS + kk + t + 4]);
                }
#pragma unroll
                for (int nt = 0; nt < 4; nt++) {
                    int cb = wn * 32 + nt * 8;
                    bfr[nt][0] = __float_as_uint(Bc[(cb + g) * CS + kk + t]);
                    bfr[nt][1] = __float_as_uint(Bc[(cb + g) * CS + kk + t + 4]);
                }
#pragma unroll
                for (int mt = 0; mt < 2; mt++)
#pragma unroll
                    for (int nt = 0; nt < 4; nt++)
                        mma_tf32(acc[mt][nt], afr[mt], bfr[nt]);
            }

            // ---- gate finalize (overlaps next chunk's cp.async flight) ----
            if (kc == 9) {
#pragma unroll
                for (int mt = 0; mt < 2; mt++) {
#pragma unroll
                    for (int h8 = 0; h8 < 2; h8++) {
                        int r = wm * 32 + mt * 16 + g + h8 * 8;
                        int nd = sNode[r];
                        int li = sLi[r], ri = sRi[r];
#pragma unroll
                        for (int nt = 0; nt < 4; nt++) {
                            int jj = wn * 32 + nt * 8 + t * 2;
                            float a0 = acc[mt][nt][h8*2+0] + bk[gidx * 128 + jj];
                            float a1 = acc[mt][nt][h8*2+1] + bk[gidx * 128 + jj + 1];
                            float* cy = &carry[mt][nt][h8*2];
                            if (gp == 0) {            // i
                                cy[0] = sigm(a0);
                                cy[1] = sigm(a1);
                            } else if (gp == 1) {     // u
                                cy[0] *= tanhf(a0);
                                cy[1] *= tanhf(a1);
                            } else if (gp == 2) {     // fl
                                cy[0] += sigm(a0) * __ldg(c_pool + (size_t)li * HV + jj);
                                cy[1] += sigm(a1) * __ldg(c_pool + (size_t)li * HV + jj + 1);
                            } else if (gp == 3) {     // fr -> c, store c
                                cy[0] += sigm(a0) * __ldg(c_pool + (size_t)ri * HV + jj);
                                cy[1] += sigm(a1) * __ldg(c_pool + (size_t)ri * HV + jj + 1);
                                if (nd >= 0)
                                    *(float2*)(out + (size_t)nd * 256 + 128 + jj) =
                                        make_float2(cy[0], cy[1]);
                            } else {                  // o -> h, store h
                                if (nd >= 0)
                                    *(float2*)(out + (size_t)nd * 256 + jj) =
                                        make_float2(sigm(a0) * tanhf(cy[0]),
                                                    sigm(a1) * tanhf(cy[1]));
                            }
                        }
                    }
                }
            }

            if (cid < 49) CP_WAIT0();
            __syncthreads();
        }
    }
}

// ---------------- launch ----------------
extern "C" void kernel_launch(void* const* d_in, const int* in_sizes, int n_in,
                              void* d_out, int out_size) {
    const float* h_pool      = (const float*)d_in[0];
    const float* c_pool      = (const float*)d_in[1];
    const float* t_pool      = (const float*)d_in[2];
    const int*   child_idx   = (const int*)d_in[3];
    const int*   parent_type = (const int*)d_in[4];
    const float* W           = (const float*)d_in[5];
    const float* b           = (const float*)d_in[6];
    float* out = (float*)d_out;

    cudaFuncSetAttribute(k_fused, cudaFuncAttributeMaxDynamicSharedMemorySize, SMBYTES);

    k_init<<<(MAXROWS + 255) / 256, 256>>>();
    k_hist<<<(NN + 255) / 256, 256>>>(parent_type);
    k_offsets<<<1, 1>>>();
    k_scatter<<<(NN + 255) / 256, 256>>>(parent_type);
    k_padW<<<(KTYPES * OGATES * DPAD + 255) / 256, 256>>>(W);
    k_fused<<<MAXTILES, THREADS, SMBYTES>>>(h_pool, c_pool, t_pool, child_idx, b, out);
}